// round 2
// baseline (speedup 1.0000x reference)
#include <cuda_runtime.h>
#include <cuda_bf16.h>
#include <cstdint>

#define STOT 200
#define ED   128
#define AD   64
#define THREADS 256
#define ROWB 272u   // padded row stride in bytes (136 bf16) -> conflict-free frags

// ---- shared memory layout (bytes) ----
#define A_HI_OFF 0u          // 256 rows x 272 B = 69632
#define A_LO_OFF 69632u
#define W_HI_OFF 139264u     // 64 rows x 272 B = 17408
#define W_LO_OFF 156672u
#define T_OFF    174080u     // 128 f32
#define C_OFF    174592u     // 64 f32
#define W2_OFF   174848u     // 64 f32
#define WARR_OFF 175104u     // 256 f32
#define PART_OFF 176128u     // 256 float2
#define B2_OFF   178176u     // 1 f32
#define SMEM_BYTES 178192u

static __device__ __forceinline__ void mma16816(
    float c[4], const uint32_t a[4], uint32_t b0, uint32_t b1)
{
    asm volatile(
        "mma.sync.aligned.m16n8k16.row.col.f32.bf16.bf16.f32 "
        "{%0,%1,%2,%3}, {%4,%5,%6,%7}, {%8,%9}, {%0,%1,%2,%3};"
        : "+f"(c[0]), "+f"(c[1]), "+f"(c[2]), "+f"(c[3])
        : "r"(a[0]), "r"(a[1]), "r"(a[2]), "r"(a[3]), "r"(b0), "r"(b1));
}

__global__ void __launch_bounds__(THREADS, 1)
attn_din_kernel(const float* __restrict__ behav,
                const float* __restrict__ target,
                const float* __restrict__ W1,
                const float* __restrict__ b1,
                const float* __restrict__ W2,
                const float* __restrict__ b2,
                float* __restrict__ out)
{
    extern __shared__ char smem[];
    const int tid  = threadIdx.x;
    const int wid  = tid >> 5;
    const int lane = tid & 31;
    const int b    = blockIdx.x;

    float* tS  = (float*)(smem + T_OFF);
    float* cS  = (float*)(smem + C_OFF);
    float* w2S = (float*)(smem + W2_OFF);
    float* wAr = (float*)(smem + WARR_OFF);

    // ---- stage small vectors ----
    if (tid < ED) tS[tid]  = target[(size_t)b * ED + tid];
    if (tid < AD) w2S[tid] = W2[tid];
    if (tid == 0) *((float*)(smem + B2_OFF)) = b2[0];

    // ---- stage behaviors: hi/lo bf16 split, padded row stride 272 B ----
    {
        const float4* bp = (const float4*)(behav + (size_t)b * (STOT * ED));
        for (int r = wid; r < STOT; r += 8) {
            float4 v = bp[r * (ED / 4) + lane];
            __nv_bfloat162 h01 = __floats2bfloat162_rn(v.x, v.y);
            __nv_bfloat162 h23 = __floats2bfloat162_rn(v.z, v.w);
            float2 f01 = __bfloat1622float2(h01);
            float2 f23 = __bfloat1622float2(h23);
            __nv_bfloat162 l01 = __floats2bfloat162_rn(v.x - f01.x, v.y - f01.y);
            __nv_bfloat162 l23 = __floats2bfloat162_rn(v.z - f23.x, v.w - f23.y);
            uint32_t off = (uint32_t)r * ROWB + (uint32_t)lane * 8u;
            *reinterpret_cast<uint2*>(smem + A_HI_OFF + off) =
                make_uint2(*(uint32_t*)&h01, *(uint32_t*)&h23);
            *reinterpret_cast<uint2*>(smem + A_LO_OFF + off) =
                make_uint2(*(uint32_t*)&l01, *(uint32_t*)&l23);
        }
        // zero-pad rows 200..255
        for (int idx = tid; idx < 56 * 32; idx += THREADS) {
            int r = 200 + (idx >> 5);
            uint32_t off = (uint32_t)r * ROWB + (uint32_t)(idx & 31) * 8u;
            *reinterpret_cast<uint2*>(smem + A_HI_OFF + off) = make_uint2(0u, 0u);
            *reinterpret_cast<uint2*>(smem + A_LO_OFF + off) = make_uint2(0u, 0u);
        }
    }
    __syncthreads();   // tS ready

    // ---- build per-batch weight W_b[a][k] = Wx + Wd + t[k]*Wm  (stored [n=a][k], hi/lo) ----
    for (int idx = tid; idx < ED * AD; idx += THREADS) {
        int k = idx >> 6, a = idx & 63;              // consecutive threads -> consecutive a (coalesced gmem)
        float w = W1[k * AD + a] + W1[(384 + k) * AD + a] + tS[k] * W1[(256 + k) * AD + a];
        __nv_bfloat16 hi = __float2bfloat16(w);
        __nv_bfloat16 lo = __float2bfloat16(w - __bfloat162float(hi));
        uint32_t off = (uint32_t)a * ROWB + (uint32_t)k * 2u;
        *reinterpret_cast<__nv_bfloat16*>(smem + W_HI_OFF + off) = hi;
        *reinterpret_cast<__nv_bfloat16*>(smem + W_LO_OFF + off) = lo;
    }

    // ---- c[a] partials: c = b1 + t @ (W_t - W_d), 4 k-quadrants ----
    {
        int a = tid & 63, q = tid >> 6;
        float acc = 0.f;
        for (int kk = 0; kk < 32; kk++) {
            int k = q * 32 + kk;
            acc += tS[k] * (W1[(128 + k) * AD + a] - W1[(384 + k) * AD + a]);
        }
        ((float*)(smem + PART_OFF))[q * 64 + a] = acc;
    }
    __syncthreads();   // A, W_b, c-partials ready

    if (tid < AD) {
        const float* p = (const float*)(smem + PART_OFF);
        cS[tid] = b1[tid] + p[tid] + p[64 + tid] + p[128 + tid] + p[192 + tid];
    }

    // ---- GEMM: warp w computes rows [32w, 32w+32) x [64] ; 3 passes hi*hi, lo*hi, hi*lo ----
    float acc[2][8][4];
#pragma unroll
    for (int m = 0; m < 2; m++)
#pragma unroll
        for (int n = 0; n < 8; n++)
#pragma unroll
            for (int i = 0; i < 4; i++) acc[m][n][i] = 0.f;

    if (wid < 7) {   // warp 7 rows 224..255 are all padding
        const int g  = lane >> 2;          // row/col group
        const int t2 = (lane & 3) * 2;     // k sub-offset
#pragma unroll
        for (int pass = 0; pass < 3; pass++) {
            const char* Ap = smem + ((pass == 1) ? A_LO_OFF : A_HI_OFF);
            const char* Wp = smem + ((pass == 2) ? W_LO_OFF : W_HI_OFF);
#pragma unroll
            for (int ks = 0; ks < 8; ks++) {
                const uint32_t kb = (uint32_t)(ks * 16 + t2) * 2u;
                uint32_t a[2][4];
#pragma unroll
                for (int m = 0; m < 2; m++) {
                    const char* base = Ap + (uint32_t)(wid * 32 + m * 16 + g) * ROWB + kb;
                    a[m][0] = *(const uint32_t*)(base);
                    a[m][1] = *(const uint32_t*)(base + 8 * ROWB);
                    a[m][2] = *(const uint32_t*)(base + 16);
                    a[m][3] = *(const uint32_t*)(base + 8 * ROWB + 16);
                }
#pragma unroll
                for (int n = 0; n < 8; n++) {
                    const char* wb = Wp + (uint32_t)(n * 8 + g) * ROWB + kb;
                    uint32_t b0 = *(const uint32_t*)(wb);
                    uint32_t b1r = *(const uint32_t*)(wb + 16);
                    mma16816(acc[0][n], a[0], b0, b1r);
                    mma16816(acc[1][n], a[1], b0, b1r);
                }
            }
        }
    }
    __syncthreads();   // cS visible to all

    // ---- epilogue: z[row] = b2 + sum_a relu(h)*W2 ; w = sigmoid(z) ----
    {
        const int g  = lane >> 2;
        const int t2 = (lane & 3) * 2;
        const float b2v = *((const float*)(smem + B2_OFF));
#pragma unroll
        for (int m = 0; m < 2; m++) {
#pragma unroll
            for (int h = 0; h < 2; h++) {
                float z = 0.f;
#pragma unroll
                for (int n = 0; n < 8; n++) {
                    int col = n * 8 + t2;
                    float h0 = fmaxf(acc[m][n][2 * h]     + cS[col],     0.f);
                    float h1 = fmaxf(acc[m][n][2 * h + 1] + cS[col + 1], 0.f);
                    z = fmaf(h0, w2S[col], z);
                    z = fmaf(h1, w2S[col + 1], z);
                }
                z += __shfl_xor_sync(0xFFFFFFFFu, z, 1);
                z += __shfl_xor_sync(0xFFFFFFFFu, z, 2);
                int s = wid * 32 + m * 16 + h * 8 + g;
                if ((lane & 3) == 0) {
                    float wgt = (s < STOT) ? (1.f / (1.f + __expf(-(z + b2v)))) : 0.f;
                    wAr[s] = wgt;
                }
            }
        }
    }
    __syncthreads();   // wAr ready

    // ---- weighted sum: out[e] = sum_s w[s] * x[s][e] (x = hi + lo) ----
    {
        int e2 = tid & 63, q = tid >> 6;
        float ax = 0.f, ay = 0.f;
        for (int i = 0; i < 50; i++) {
            int s = q * 50 + i;
            uint32_t off = (uint32_t)s * ROWB + (uint32_t)e2 * 4u;
            __nv_bfloat162 h2 = *reinterpret_cast<const __nv_bfloat162*>(smem + A_HI_OFF + off);
            __nv_bfloat162 l2 = *reinterpret_cast<const __nv_bfloat162*>(smem + A_LO_OFF + off);
            float2 fh = __bfloat1622float2(h2);
            float2 fl = __bfloat1622float2(l2);
            float ws = wAr[s];
            ax = fmaf(ws, fh.x + fl.x, ax);
            ay = fmaf(ws, fh.y + fl.y, ay);
        }
        ((float2*)(smem + PART_OFF))[q * 64 + e2] = make_float2(ax, ay);
    }
    __syncthreads();

    if (tid < 64) {
        const float2* p = (const float2*)(smem + PART_OFF);
        float2 r0 = p[tid], r1 = p[64 + tid], r2 = p[128 + tid], r3 = p[192 + tid];
        float2 o = make_float2(r0.x + r1.x + r2.x + r3.x, r0.y + r1.y + r2.y + r3.y);
        *reinterpret_cast<float2*>(out + (size_t)b * ED + tid * 2) = o;
    }
}

extern "C" void kernel_launch(void* const* d_in, const int* in_sizes, int n_in,
                              void* d_out, int out_size)
{
    const float* behav  = (const float*)d_in[0];
    const float* target = (const float*)d_in[1];
    const float* W1     = (const float*)d_in[2];
    const float* b1     = (const float*)d_in[3];
    const float* W2     = (const float*)d_in[4];
    const float* b2     = (const float*)d_in[5];
    float* out = (float*)d_out;

    const int B = in_sizes[1] / ED;   // 2048

    static bool attr_set = false;
    if (!attr_set) {
        cudaFuncSetAttribute(attn_din_kernel,
                             cudaFuncAttributeMaxDynamicSharedMemorySize, (int)SMEM_BYTES);
        attr_set = true;
    }
    attn_din_kernel<<<B, THREADS, SMEM_BYTES>>>(behav, target, W1, b1, W2, b2, out);
}